// round 1
// baseline (speedup 1.0000x reference)
#include <cuda_runtime.h>
#include <math.h>

#define Bn  4
#define Hn  16
#define Sn  2048
#define DKn 128
#define NBH (Bn * Hn)
#define CTX_ELEMS ((size_t)NBH * Sn * DKn)   // 16,777,216
#define ATT_ELEMS ((size_t)NBH * Sn * Sn)    // 268,435,456

// ---------------------------------------------------------------------------
// Kernel 1: raw scaled scores S = Q K^T / sqrt(dk), lower-triangle tiles only.
// Classic 128x128x(BK=16) SGEMM, 256 threads, 8x8 micro-tile per thread.
// Writes raw scores into the attn region of d_out (in-place staging).
// ---------------------------------------------------------------------------
__global__ __launch_bounds__(256, 2)
void k_scores(const float* __restrict__ Q, const float* __restrict__ K,
              float* __restrict__ attn)
{
    const int p  = blockIdx.x;       // 0..135 lower-triangle tile pair
    const int bh = blockIdx.y;       // 0..63
    int qt = (int)((sqrtf(8.0f * (float)p + 1.0f) - 1.0f) * 0.5f);
    while ((qt + 1) * (qt + 2) / 2 <= p) qt++;
    while (qt * (qt + 1) / 2 > p) qt--;
    const int kt = p - qt * (qt + 1) / 2;

    __shared__ float As[16][128];    // Q tile, transposed [d][m]
    __shared__ float Bs[16][128];    // K tile, transposed [d][n]

    const int tid = threadIdx.x;
    const int tx  = tid & 15;
    const int ty  = tid >> 4;

    const float* Qb = Q + ((size_t)bh * Sn + (size_t)qt * 128) * DKn;
    const float* Kb = K + ((size_t)bh * Sn + (size_t)kt * 128) * DKn;

    float acc[8][8];
    #pragma unroll
    for (int i = 0; i < 8; i++)
        #pragma unroll
        for (int j = 0; j < 8; j++) acc[i][j] = 0.0f;

    for (int d0 = 0; d0 < DKn; d0 += 16) {
        #pragma unroll
        for (int r = 0; r < 2; r++) {
            int v  = tid + r * 256;          // 0..511 (128 rows x 4 float4s)
            int m  = v >> 2;
            int dv = (v & 3) << 2;
            float4 qa = *(const float4*)(Qb + (size_t)m * DKn + d0 + dv);
            As[dv + 0][m] = qa.x; As[dv + 1][m] = qa.y;
            As[dv + 2][m] = qa.z; As[dv + 3][m] = qa.w;
            float4 kb = *(const float4*)(Kb + (size_t)m * DKn + d0 + dv);
            Bs[dv + 0][m] = kb.x; Bs[dv + 1][m] = kb.y;
            Bs[dv + 2][m] = kb.z; Bs[dv + 3][m] = kb.w;
        }
        __syncthreads();
        #pragma unroll
        for (int kk = 0; kk < 16; kk++) {
            float4 a0 = *(const float4*)&As[kk][ty * 8];
            float4 a1 = *(const float4*)&As[kk][ty * 8 + 4];
            float4 b0 = *(const float4*)&Bs[kk][tx * 8];
            float4 b1 = *(const float4*)&Bs[kk][tx * 8 + 4];
            float a[8] = {a0.x, a0.y, a0.z, a0.w, a1.x, a1.y, a1.z, a1.w};
            float b[8] = {b0.x, b0.y, b0.z, b0.w, b1.x, b1.y, b1.z, b1.w};
            #pragma unroll
            for (int i = 0; i < 8; i++)
                #pragma unroll
                for (int j = 0; j < 8; j++)
                    acc[i][j] = fmaf(a[i], b[j], acc[i][j]);
        }
        __syncthreads();
    }

    const float scale = 0.088388347648318447f;   // 1/sqrt(128)
    float* Cb = attn + ((size_t)bh * Sn + (size_t)qt * 128) * Sn + (size_t)kt * 128;
    #pragma unroll
    for (int i = 0; i < 8; i++) {
        int row = ty * 8 + i;
        float4 w0 = make_float4(acc[i][0] * scale, acc[i][1] * scale,
                                acc[i][2] * scale, acc[i][3] * scale);
        float4 w1 = make_float4(acc[i][4] * scale, acc[i][5] * scale,
                                acc[i][6] * scale, acc[i][7] * scale);
        *(float4*)(Cb + (size_t)row * Sn + tx * 8)     = w0;
        *(float4*)(Cb + (size_t)row * Sn + tx * 8 + 4) = w1;
    }
}

// ---------------------------------------------------------------------------
// Kernel 2: row softmax in-place. One block per (bh, q) row; row cached in
// smem. Elements k > q are written as exact 0 (matches exp(-1e9-max)=0 in f32).
// ---------------------------------------------------------------------------
__global__ __launch_bounds__(256)
void k_softmax(float* __restrict__ attn)
{
    const int    row  = blockIdx.x;           // 0 .. NBH*Sn-1
    const int    q    = row & (Sn - 1);
    const size_t base = (size_t)row * Sn;
    const int    L    = q + 1;

    __shared__ float buf[Sn];
    __shared__ float red[8];

    const int tid  = threadIdx.x;
    const int lane = tid & 31;
    const int wid  = tid >> 5;

    float mx = -3.4e38f;
    for (int i = tid; i < L; i += 256) {
        float v = attn[base + i];
        buf[i] = v;
        mx = fmaxf(mx, v);
    }
    #pragma unroll
    for (int o = 16; o > 0; o >>= 1)
        mx = fmaxf(mx, __shfl_xor_sync(0xffffffffu, mx, o));
    if (lane == 0) red[wid] = mx;
    __syncthreads();
    float m = red[0];
    #pragma unroll
    for (int w = 1; w < 8; w++) m = fmaxf(m, red[w]);
    __syncthreads();   // everyone done reading red before it is reused

    float s = 0.0f;
    for (int i = tid; i < L; i += 256) {
        float e = __expf(buf[i] - m);
        buf[i] = e;
        s += e;
    }
    #pragma unroll
    for (int o = 16; o > 0; o >>= 1)
        s += __shfl_xor_sync(0xffffffffu, s, o);
    if (lane == 0) red[wid] = s;
    __syncthreads();
    float tot = 0.0f;
    #pragma unroll
    for (int w = 0; w < 8; w++) tot += red[w];
    const float inv = 1.0f / tot;

    for (int i = tid; i < L; i += 256)
        attn[base + i] = buf[i] * inv;
    for (int i = L + tid; i < Sn; i += 256)
        attn[base + i] = 0.0f;
}

// ---------------------------------------------------------------------------
// Kernel 3: context = attn @ V, causal (k-loop stops after diagonal block).
// 128x128x(BK=32) SGEMM per block; zeros above diagonal contribute nothing.
// ---------------------------------------------------------------------------
__global__ __launch_bounds__(256, 2)
void k_context(const float* __restrict__ attn, const float* __restrict__ V,
               float* __restrict__ ctx)
{
    const int qt = (Sn / 128 - 1) - blockIdx.x;   // longest blocks first
    const int bh = blockIdx.y;

    __shared__ float As[32][128];   // attn tile, transposed [k][m]
    __shared__ float Vs[32][128];   // V tile, natural [k][d]

    const int tid = threadIdx.x;
    const int tx  = tid & 15;
    const int ty  = tid >> 4;

    const float* Ab = attn + ((size_t)bh * Sn + (size_t)qt * 128) * Sn;
    const float* Vb = V + (size_t)bh * Sn * DKn;

    float acc[8][8];
    #pragma unroll
    for (int i = 0; i < 8; i++)
        #pragma unroll
        for (int j = 0; j < 8; j++) acc[i][j] = 0.0f;

    const int kmax = (qt + 1) * 128;
    for (int k0 = 0; k0 < kmax; k0 += 32) {
        #pragma unroll
        for (int r = 0; r < 4; r++) {
            int v = tid + r * 256;           // 0..1023
            // attn tile: 128 rows x 8 float4s per row
            int m  = v >> 3;
            int kv = (v & 7) << 2;
            float4 a = *(const float4*)(Ab + (size_t)m * Sn + k0 + kv);
            As[kv + 0][m] = a.x; As[kv + 1][m] = a.y;
            As[kv + 2][m] = a.z; As[kv + 3][m] = a.w;
            // V tile: 32 rows x 32 float4s per row
            int kr = v >> 5;
            int dv = (v & 31) << 2;
            *(float4*)&Vs[kr][dv] =
                *(const float4*)(Vb + (size_t)(k0 + kr) * DKn + dv);
        }
        __syncthreads();
        #pragma unroll
        for (int kk = 0; kk < 32; kk++) {
            float4 a0 = *(const float4*)&As[kk][ty * 8];
            float4 a1 = *(const float4*)&As[kk][ty * 8 + 4];
            float4 b0 = *(const float4*)&Vs[kk][tx * 8];
            float4 b1 = *(const float4*)&Vs[kk][tx * 8 + 4];
            float a[8] = {a0.x, a0.y, a0.z, a0.w, a1.x, a1.y, a1.z, a1.w};
            float b[8] = {b0.x, b0.y, b0.z, b0.w, b1.x, b1.y, b1.z, b1.w};
            #pragma unroll
            for (int i = 0; i < 8; i++)
                #pragma unroll
                for (int j = 0; j < 8; j++)
                    acc[i][j] = fmaf(a[i], b[j], acc[i][j]);
        }
        __syncthreads();
    }

    float* Cb = ctx + ((size_t)bh * Sn + (size_t)qt * 128) * DKn;
    #pragma unroll
    for (int i = 0; i < 8; i++) {
        int row = ty * 8 + i;
        float4 w0 = make_float4(acc[i][0], acc[i][1], acc[i][2], acc[i][3]);
        float4 w1 = make_float4(acc[i][4], acc[i][5], acc[i][6], acc[i][7]);
        *(float4*)(Cb + (size_t)row * DKn + tx * 8)     = w0;
        *(float4*)(Cb + (size_t)row * DKn + tx * 8 + 4) = w1;
    }
}

// ---------------------------------------------------------------------------
// Launch. d_out layout: [context (16,777,216 f32)][attn (268,435,456 f32)].
// Raw scores are staged directly in the attn region (no scratch needed).
// ---------------------------------------------------------------------------
extern "C" void kernel_launch(void* const* d_in, const int* in_sizes, int n_in,
                              void* d_out, int out_size)
{
    (void)in_sizes; (void)n_in; (void)out_size;
    const float* Q = (const float*)d_in[0];
    const float* K = (const float*)d_in[1];
    const float* V = (const float*)d_in[2];
    // d_in[3] = attn_mask (causal, known statically) — unused.

    float* out  = (float*)d_out;
    float* ctx  = out;
    float* attn = out + CTX_ELEMS;

    dim3 g1(136, NBH);            // lower-triangle 128x128 tiles
    k_scores<<<g1, 256>>>(Q, K, attn);

    k_softmax<<<NBH * Sn, 256>>>(attn);

    dim3 g3(Sn / 128, NBH);
    k_context<<<g3, 256>>>(attn, V, ctx);
}

// round 3
// speedup vs baseline: 1.6792x; 1.6792x over previous
#include <cuda_runtime.h>
#include <cuda_bf16.h>
#include <cstdint>

#define Bn  4
#define Hn  16
#define Sn  2048
#define DKn 128
#define NBH (Bn * Hn)
#define CTX_ELEMS ((size_t)NBH * Sn * DKn)

// ---------------------------------------------------------------------------
// Swizzled 128x128 bf16 tile layout: row-major, 256B rows; 16B units XORed
// with (row&7) -> conflict-free STS + conflict-free ldmatrix.
// ---------------------------------------------------------------------------
__device__ __forceinline__ uint32_t swz(int r, int c) {   // byte offset
    int u = c >> 3;
    u = (u & 8) | ((u ^ r) & 7);
    return (uint32_t)(r * 256 + u * 16 + (c & 7) * 2);
}
__device__ __forceinline__ uint32_t smem_u32(const void* p) {
    uint32_t a;
    asm("{ .reg .u64 t; cvta.to.shared.u64 t, %1; cvt.u32.u64 %0, t; }" : "=r"(a) : "l"(p));
    return a;
}
__device__ __forceinline__ uint32_t pack2f(float a, float b) {
    __nv_bfloat162 h = __floats2bfloat162_rn(a, b);
    return *(uint32_t*)&h;
}
__device__ __forceinline__ void ldsm4(uint32_t* r, uint32_t addr) {
    asm volatile("ldmatrix.sync.aligned.m8n8.x4.shared.b16 {%0,%1,%2,%3}, [%4];"
                 : "=r"(r[0]), "=r"(r[1]), "=r"(r[2]), "=r"(r[3]) : "r"(addr));
}
__device__ __forceinline__ void mma16816(float* d, const uint32_t* a, const uint32_t* b) {
    asm volatile(
        "mma.sync.aligned.m16n8k16.row.col.f32.bf16.bf16.f32 "
        "{%0,%1,%2,%3}, {%4,%5,%6,%7}, {%8,%9}, {%0,%1,%2,%3};"
        : "+f"(d[0]), "+f"(d[1]), "+f"(d[2]), "+f"(d[3])
        : "r"(a[0]), "r"(a[1]), "r"(a[2]), "r"(a[3]), "r"(b[0]), "r"(b[1]));
}

// SMEM: 4 tiles of 32KB (Ahi, Alo, Bhi, Blo)
#define SM_AHI 0
#define SM_ALO 32768
#define SM_BHI 65536
#define SM_BLO 98304
#define SMEM_SZ 131072

// Load 128x128 f32 tile (row stride rs), split bf16 hi/lo, store swizzled.
__device__ __forceinline__ void load_split(const float* __restrict__ g, int rs,
                                           char* hi, char* lo, float scale) {
    for (int i = threadIdx.x; i < 4096; i += 256) {
        int r  = i >> 5;
        int c4 = (i & 31) << 2;
        float4 v = *(const float4*)(g + (size_t)r * rs + c4);
        v.x *= scale; v.y *= scale; v.z *= scale; v.w *= scale;
        __nv_bfloat16 h0 = __float2bfloat16(v.x), h1 = __float2bfloat16(v.y),
                      h2 = __float2bfloat16(v.z), h3 = __float2bfloat16(v.w);
        uint32_t off = swz(r, c4);
        uint2 hp, lp;
        hp.x = pack2f(v.x, v.y); hp.y = pack2f(v.z, v.w);
        // recompute hi as rounded value for exact residual
        lp.x = pack2f(v.x - __bfloat162float(h0), v.y - __bfloat162float(h1));
        lp.y = pack2f(v.z - __bfloat162float(h2), v.w - __bfloat162float(h3));
        *(uint2*)(hi + off) = hp;
        *(uint2*)(lo + off) = lp;
    }
}

// Load V tile [k0..k0+128) x d[0..128) transposed -> tile rows=d, cols=k.
// Coalesced LDG (lanes across d), conflict-free STS.128.
__device__ __forceinline__ void load_vT(const float* __restrict__ Vk0,
                                        char* hi, char* lo) {
    const int w = threadIdx.x >> 5, lane = threadIdx.x & 31;
    const int d  = (w & 3) * 32 + lane;
    const int kh = (w >> 2) * 64;
    #pragma unroll
    for (int jj = 0; jj < 8; jj++) {
        int k8 = kh + jj * 8;
        float f[8];
        #pragma unroll
        for (int j = 0; j < 8; j++)
            f[j] = Vk0[(size_t)(k8 + j) * DKn + d];
        uint4 hp, lp;
        uint32_t* hq = (uint32_t*)&hp;
        uint32_t* lq = (uint32_t*)&lp;
        #pragma unroll
        for (int p = 0; p < 4; p++) {
            float a = f[2 * p], b = f[2 * p + 1];
            hq[p] = pack2f(a, b);
            lq[p] = pack2f(a - __bfloat162float(__float2bfloat16(a)),
                           b - __bfloat162float(__float2bfloat16(b)));
        }
        uint32_t off = swz(d, k8);
        *(uint4*)(hi + off) = hp;
        *(uint4*)(lo + off) = lp;
    }
}

// One 128x128x128 bf16x3 tile MMA: A,B tiles in smem, acc[2][8][4] registers.
__device__ __forceinline__ void tile_mma(uint32_t smb, int warp_m, int warp_n,
                                         float acc[2][8][4]) {
    const int lane = threadIdx.x & 31;
    // per-lane ldmatrix row/col offsets
    const int a_r = (lane & 7) + ((lane >> 3) & 1) * 8;   // + m0
    const int a_c = (lane >> 4) * 8;                      // + k0
    const int b_r = (lane & 7) + (lane >> 4) * 8;         // + n0
    const int b_c = ((lane >> 3) & 1) * 8;                // + k0
    const int m0 = warp_m * 32;
    const int n0 = warp_n * 64;

    for (int k0 = 0; k0 < 128; k0 += 16) {
        uint32_t Ah[2][4], Al[2][4], Bh[4][4], Bl[4][4];
        #pragma unroll
        for (int mf = 0; mf < 2; mf++) {
            uint32_t off = swz(m0 + mf * 16 + a_r, k0 + a_c);
            ldsm4(Ah[mf], smb + SM_AHI + off);
            ldsm4(Al[mf], smb + SM_ALO + off);
        }
        #pragma unroll
        for (int np = 0; np < 4; np++) {
            uint32_t off = swz(n0 + np * 16 + b_r, k0 + b_c);
            ldsm4(Bh[np], smb + SM_BHI + off);
            ldsm4(Bl[np], smb + SM_BLO + off);
        }
        #pragma unroll
        for (int mf = 0; mf < 2; mf++)
            #pragma unroll
            for (int nf = 0; nf < 8; nf++) {
                const uint32_t* bh = &Bh[nf >> 1][(nf & 1) * 2];
                const uint32_t* bl = &Bl[nf >> 1][(nf & 1) * 2];
                mma16816(acc[mf][nf], Ah[mf], bh);
                mma16816(acc[mf][nf], Ah[mf], bl);
                mma16816(acc[mf][nf], Al[mf], bh);
            }
    }
}

// ---------------------------------------------------------------------------
// Kernel 1: scores = Q K^T / sqrt(dk). Grid (24, 64): qt<8 one block per
// row-block, qt>=8 two blocks (kt halves). Q pre-scaled.
// ---------------------------------------------------------------------------
__global__ __launch_bounds__(256, 1)
void k_scores_mma(const float* __restrict__ Q, const float* __restrict__ K,
                  float* __restrict__ attn)
{
    extern __shared__ char sm[];
    const uint32_t smb = smem_u32(sm);
    const int tid = threadIdx.x, wid = tid >> 5, lane = tid & 31;
    const int warp_m = wid & 3, warp_n = wid >> 2;

    const int bx = 23 - (int)blockIdx.x;
    const int bh = blockIdx.y;
    int qt, kb, ke;
    if (bx < 8) { qt = bx; kb = 0; ke = qt + 1; }
    else {
        int i = bx - 8; qt = 8 + (i >> 1);
        int L = qt + 1, h = (L + 1) >> 1;
        if (i & 1) { kb = h; ke = L; } else { kb = 0; ke = h; }
    }

    load_split(Q + ((size_t)bh * Sn + (size_t)qt * 128) * DKn, DKn,
               sm + SM_AHI, sm + SM_ALO, 0.088388347648318447f);

    for (int kt = kb; kt < ke; kt++) {
        load_split(K + ((size_t)bh * Sn + (size_t)kt * 128) * DKn, DKn,
                   sm + SM_BHI, sm + SM_BLO, 1.0f);
        __syncthreads();

        float acc[2][8][4];
        #pragma unroll
        for (int mf = 0; mf < 2; mf++)
            #pragma unroll
            for (int nf = 0; nf < 8; nf++)
                #pragma unroll
                for (int j = 0; j < 4; j++) acc[mf][nf][j] = 0.0f;

        tile_mma(smb, warp_m, warp_n, acc);
        __syncthreads();   // B smem reusable next iteration

        float* dst = attn + ((size_t)bh * Sn + (size_t)qt * 128) * Sn
                   + (size_t)kt * 128;
        const int rb = warp_m * 32 + (lane >> 2);
        const int cb = warp_n * 64 + (lane & 3) * 2;
        #pragma unroll
        for (int mf = 0; mf < 2; mf++)
            #pragma unroll
            for (int nf = 0; nf < 8; nf++) {
                float* p0 = dst + (size_t)(rb + mf * 16) * Sn + cb + nf * 8;
                float* p1 = p0 + 8 * Sn;
                *(float2*)p0 = make_float2(acc[mf][nf][0], acc[mf][nf][1]);
                *(float2*)p1 = make_float2(acc[mf][nf][2], acc[mf][nf][3]);
            }
    }
}

// ---------------------------------------------------------------------------
// Kernel 2: row softmax (float4-vectorized), exact zeros above diagonal.
// ---------------------------------------------------------------------------
__global__ __launch_bounds__(256)
void k_softmax(float* __restrict__ attn)
{
    const int row = blockIdx.x;
    const int q   = row & (Sn - 1);
    const int L   = q + 1;
    const int L4  = (L + 3) >> 2;
    float4* a4 = (float4*)attn + (size_t)row * (Sn / 4);

    __shared__ float4 buf[Sn / 4];
    __shared__ float  red[8];

    const int tid = threadIdx.x, lane = tid & 31, wid = tid >> 5;

    float mx = -3.4e38f;
    for (int i = tid; i < L4; i += 256) {
        float4 v = a4[i];
        int k0 = i << 2;
        if (k0 + 1 >= L) v.y = -1e30f;
        if (k0 + 2 >= L) v.z = -1e30f;
        if (k0 + 3 >= L) v.w = -1e30f;
        buf[i] = v;
        mx = fmaxf(mx, fmaxf(fmaxf(v.x, v.y), fmaxf(v.z, v.w)));
    }
    #pragma unroll
    for (int o = 16; o > 0; o >>= 1)
        mx = fmaxf(mx, __shfl_xor_sync(0xffffffffu, mx, o));
    if (lane == 0) red[wid] = mx;
    __syncthreads();
    float m = red[0];
    #pragma unroll
    for (int w = 1; w < 8; w++) m = fmaxf(m, red[w]);
    __syncthreads();

    float s = 0.0f;
    for (int i = tid; i < L4; i += 256) {
        float4 v = buf[i];
        v.x = __expf(v.x - m); v.y = __expf(v.y - m);
        v.z = __expf(v.z - m); v.w = __expf(v.w - m);
        buf[i] = v;
        s += (v.x + v.y) + (v.z + v.w);
    }
    #pragma unroll
    for (int o = 16; o > 0; o >>= 1)
        s += __shfl_xor_sync(0xffffffffu, s, o);
    if (lane == 0) red[wid] = s;
    __syncthreads();
    float tot = 0.0f;
    #pragma unroll
    for (int w = 0; w < 8; w++) tot += red[w];
    const float inv = 1.0f / tot;

    const float4 z4 = make_float4(0.f, 0.f, 0.f, 0.f);
    for (int i = tid; i < Sn / 4; i += 256) {
        if (i < L4) {
            float4 v = buf[i];
            v.x *= inv; v.y *= inv; v.z *= inv; v.w *= inv;
            a4[i] = v;
        } else {
            a4[i] = z4;
        }
    }
}

// ---------------------------------------------------------------------------
// Kernel 3: context = attn @ V. One block per (qt, bh); acc persists across
// kt in registers; V transposed at load.
// ---------------------------------------------------------------------------
__global__ __launch_bounds__(256, 1)
void k_context_mma(const float* __restrict__ attn, const float* __restrict__ V,
                   float* __restrict__ ctx)
{
    extern __shared__ char sm[];
    const uint32_t smb = smem_u32(sm);
    const int tid = threadIdx.x, wid = tid >> 5, lane = tid & 31;
    const int warp_m = wid & 3, warp_n = wid >> 2;

    const int qt = (Sn / 128 - 1) - (int)blockIdx.x;   // big first
    const int bh = blockIdx.y;

    const float* Ab = attn + ((size_t)bh * Sn + (size_t)qt * 128) * Sn;
    const float* Vb = V + (size_t)bh * Sn * DKn;

    float acc[2][8][4];
    #pragma unroll
    for (int mf = 0; mf < 2; mf++)
        #pragma unroll
        for (int nf = 0; nf < 8; nf++)
            #pragma unroll
            for (int j = 0; j < 4; j++) acc[mf][nf][j] = 0.0f;

    for (int kt = 0; kt <= qt; kt++) {
        load_split(Ab + (size_t)kt * 128, Sn, sm + SM_AHI, sm + SM_ALO, 1.0f);
        load_vT(Vb + (size_t)kt * 128 * DKn, sm + SM_BHI, sm + SM_BLO);
        __syncthreads();
        tile_mma(smb, warp_m, warp_n, acc);
        __syncthreads();
    }

    float* dst = ctx + ((size_t)bh * Sn + (size_t)qt * 128) * DKn;
    const int rb = warp_m * 32 + (lane >> 2);
    const int cb = warp_n * 64 + (lane & 3) * 2;
    #pragma unroll
    for (int mf = 0; mf < 2; mf++)
        #pragma unroll
        for (int nf = 0; nf < 8; nf++) {
            float* p0 = dst + (size_t)(rb + mf * 16) * DKn + cb + nf * 8;
            float* p1 = p0 + 8 * DKn;
            *(float2*)p0 = make_float2(acc[mf][nf][0], acc[mf][nf][1]);
            *(float2*)p1 = make_float2(acc[mf][nf][2], acc[mf][nf][3]);
        }
}

// ---------------------------------------------------------------------------
extern "C" void kernel_launch(void* const* d_in, const int* in_sizes, int n_in,
                              void* d_out, int out_size)
{
    (void)in_sizes; (void)n_in; (void)out_size;
    const float* Q = (const float*)d_in[0];
    const float* K = (const float*)d_in[1];
    const float* V = (const float*)d_in[2];
    // d_in[3] = attn_mask (causal, known statically) — unused.

    float* out  = (float*)d_out;
    float* ctx  = out;
    float* attn = out + CTX_ELEMS;

    cudaFuncSetAttribute(k_scores_mma,  cudaFuncAttributeMaxDynamicSharedMemorySize, SMEM_SZ);
    cudaFuncSetAttribute(k_context_mma, cudaFuncAttributeMaxDynamicSharedMemorySize, SMEM_SZ);

    k_scores_mma<<<dim3(24, NBH), 256, SMEM_SZ>>>(Q, K, attn);
    k_softmax<<<NBH * Sn, 256>>>(attn);
    k_context_mma<<<dim3(Sn / 128, NBH), 256, SMEM_SZ>>>(attn, V, ctx);
}

// round 4
// speedup vs baseline: 2.3521x; 1.4008x over previous
#include <cuda_runtime.h>
#include <cuda_bf16.h>
#include <cstdint>

#define Bn  4
#define Hn  16
#define Sn  2048
#define DKn 128
#define NBH (Bn * Hn)
#define NT  16                        // 128-row tiles per sequence
#define CTX_ELEMS ((size_t)NBH * Sn * DKn)

// log2(e)/sqrt(128): folded into Q so K1 epilogue is a bare exp2.
#define QSCALE ((float)(1.4426950408889634 / 11.313708498984761))

// ---------------- scratch (static device allocations are allowed) ----------
__device__ __align__(16) char g_Qhi[1u << 25];   // 32MB each: 64 bh x 16 tiles x 32KB
__device__ __align__(16) char g_Qlo[1u << 25];
__device__ __align__(16) char g_Khi[1u << 25];
__device__ __align__(16) char g_Klo[1u << 25];
__device__ __align__(16) char g_Vhi[1u << 25];   // V transposed per tile: [d][k]
__device__ __align__(16) char g_Vlo[1u << 25];
__device__ float g_rowsum[NBH * Sn];

#define BLOB(bh, t) (((size_t)((bh) * NT + (t))) << 15)

// ---------------- helpers ----------------
__device__ __forceinline__ uint32_t swz(int r, int c) {   // byte offset in 32KB tile
    int u = c >> 3;
    u = (u & 8) | ((u ^ r) & 7);
    return (uint32_t)(r * 256 + u * 16 + (c & 7) * 2);
}
__device__ __forceinline__ uint32_t smem_u32(const void* p) {
    uint32_t a;
    asm("{ .reg .u64 t; cvta.to.shared.u64 t, %1; cvt.u32.u64 %0, t; }" : "=r"(a) : "l"(p));
    return a;
}
__device__ __forceinline__ uint32_t pack2f(float a, float b) {
    __nv_bfloat162 h = __floats2bfloat162_rn(a, b);
    return *(uint32_t*)&h;
}
__device__ __forceinline__ void ldsm4(uint32_t* r, uint32_t addr) {
    asm volatile("ldmatrix.sync.aligned.m8n8.x4.shared.b16 {%0,%1,%2,%3}, [%4];"
                 : "=r"(r[0]), "=r"(r[1]), "=r"(r[2]), "=r"(r[3]) : "r"(addr));
}
__device__ __forceinline__ void mma16816(float* d, const uint32_t* a, const uint32_t* b) {
    asm volatile(
        "mma.sync.aligned.m16n8k16.row.col.f32.bf16.bf16.f32 "
        "{%0,%1,%2,%3}, {%4,%5,%6,%7}, {%8,%9}, {%0,%1,%2,%3};"
        : "+f"(d[0]), "+f"(d[1]), "+f"(d[2]), "+f"(d[3])
        : "r"(a[0]), "r"(a[1]), "r"(a[2]), "r"(a[3]), "r"(b[0]), "r"(b[1]));
}
__device__ __forceinline__ void cpa16(uint32_t s, const void* g) {
    asm volatile("cp.async.cg.shared.global [%0], [%1], 16;" :: "r"(s), "l"(g));
}
#define CP_COMMIT() asm volatile("cp.async.commit_group;" ::: "memory")
#define CP_WAIT(N)  asm volatile("cp.async.wait_group %0;" :: "n"(N) : "memory")

// copy one 32KB prepped tile blob into smem (8 chunks of 16B per thread)
__device__ __forceinline__ void cp_blob32k(uint32_t sdst, const char* gsrc) {
    #pragma unroll
    for (int j = 0; j < 8; j++) {
        uint32_t off = (uint32_t)(threadIdx.x + j * 256) * 16;
        cpa16(sdst + off, gsrc + off);
    }
}

// bf16x3 128x128x128 tile MMA (hi*hi + hi*lo + lo*hi), accumulating.
__device__ __forceinline__ void tile_mma(uint32_t aHi, uint32_t aLo,
                                         uint32_t bHi, uint32_t bLo,
                                         float acc[2][8][4],
                                         int warp_m, int warp_n, int lane) {
    const int a_r = (lane & 7) + ((lane >> 3) & 1) * 8;
    const int a_c = (lane >> 4) * 8;
    const int b_r = (lane & 7) + (lane >> 4) * 8;
    const int b_c = ((lane >> 3) & 1) * 8;
    const int m0 = warp_m * 32;
    const int n0 = warp_n * 64;
    #pragma unroll
    for (int k0 = 0; k0 < 128; k0 += 16) {
        uint32_t Ah[2][4], Al[2][4], Bh[4][4], Bl[4][4];
        #pragma unroll
        for (int mf = 0; mf < 2; mf++) {
            uint32_t off = swz(m0 + mf * 16 + a_r, k0 + a_c);
            ldsm4(Ah[mf], aHi + off);
            ldsm4(Al[mf], aLo + off);
        }
        #pragma unroll
        for (int np = 0; np < 4; np++) {
            uint32_t off = swz(n0 + np * 16 + b_r, k0 + b_c);
            ldsm4(Bh[np], bHi + off);
            ldsm4(Bl[np], bLo + off);
        }
        #pragma unroll
        for (int mf = 0; mf < 2; mf++)
            #pragma unroll
            for (int nf = 0; nf < 8; nf++) {
                const uint32_t* bh = &Bh[nf >> 1][(nf & 1) * 2];
                const uint32_t* bl = &Bl[nf >> 1][(nf & 1) * 2];
                mma16816(acc[mf][nf], Ah[mf], bh);
                mma16816(acc[mf][nf], Ah[mf], bl);
                mma16816(acc[mf][nf], Al[mf], bh);
            }
    }
}

// ---------------------------------------------------------------------------
// Prep: split Q (pre-scaled) and K into bf16 hi/lo swizzled tile blobs.
// ---------------------------------------------------------------------------
__global__ __launch_bounds__(256)
void k_prep_qk(const float* __restrict__ Q, const float* __restrict__ K)
{
    const int bx = blockIdx.x, bh = blockIdx.y;
    const bool isQ = bx < NT;
    const int t = isQ ? bx : bx - NT;
    const float sc = isQ ? QSCALE : 1.0f;
    const float* src = (isQ ? Q : K) + ((size_t)bh * Sn + (size_t)t * 128) * DKn;
    char* hi = (isQ ? g_Qhi : g_Khi) + BLOB(bh, t);
    char* lo = (isQ ? g_Qlo : g_Klo) + BLOB(bh, t);

    for (int i = threadIdx.x; i < 4096; i += 256) {
        int r = i >> 5, c4 = (i & 31) << 2;
        float4 v = *(const float4*)(src + (size_t)r * DKn + c4);
        v.x *= sc; v.y *= sc; v.z *= sc; v.w *= sc;
        uint32_t off = swz(r, c4);
        uint2 hp, lp;
        hp.x = pack2f(v.x, v.y); hp.y = pack2f(v.z, v.w);
        lp.x = pack2f(v.x - __bfloat162float(__float2bfloat16(v.x)),
                      v.y - __bfloat162float(__float2bfloat16(v.y)));
        lp.y = pack2f(v.z - __bfloat162float(__float2bfloat16(v.z)),
                      v.w - __bfloat162float(__float2bfloat16(v.w)));
        *(uint2*)(hi + off) = hp;
        *(uint2*)(lo + off) = lp;
    }
}

// Prep: V transposed per tile -> blob rows = d, cols = k (B operand image).
__global__ __launch_bounds__(256)
void k_prep_v(const float* __restrict__ V)
{
    const int t = blockIdx.x, bh = blockIdx.y;
    const float* src = V + ((size_t)bh * Sn + (size_t)t * 128) * DKn;
    char* hi = g_Vhi + BLOB(bh, t);
    char* lo = g_Vlo + BLOB(bh, t);

    const int w = threadIdx.x >> 5, lane = threadIdx.x & 31;
    const int d = (w & 3) * 32 + lane;
    const int kh = (w >> 2) * 64;
    #pragma unroll
    for (int jj = 0; jj < 8; jj++) {
        int k8 = kh + jj * 8;
        float f[8];
        #pragma unroll
        for (int j = 0; j < 8; j++)
            f[j] = src[(size_t)(k8 + j) * DKn + d];
        uint4 hp, lp;
        uint32_t* hq = (uint32_t*)&hp;
        uint32_t* lq = (uint32_t*)&lp;
        #pragma unroll
        for (int p = 0; p < 4; p++) {
            float a = f[2 * p], b = f[2 * p + 1];
            hq[p] = pack2f(a, b);
            lq[p] = pack2f(a - __bfloat162float(__float2bfloat16(a)),
                           b - __bfloat162float(__float2bfloat16(b)));
        }
        uint32_t off = swz(d, k8);
        *(uint4*)(hi + off) = hp;
        *(uint4*)(lo + off) = lp;
    }
}

// Zero-fill strictly-upper attn tiles (kt > qt): 120 tiles per bh.
__global__ __launch_bounds__(256)
void k_zero_upper(float* __restrict__ attn)
{
    int p = blockIdx.x, bh = blockIdx.y;
    int qt = 0;
    while (p >= NT - 1 - qt) { p -= NT - 1 - qt; qt++; }
    const int kt = qt + 1 + p;
    float* dst = attn + ((size_t)bh * Sn + (size_t)qt * 128) * Sn + (size_t)kt * 128;
    const float4 z = make_float4(0.f, 0.f, 0.f, 0.f);
    for (int i = threadIdx.x; i < 4096; i += 256) {
        int r = i >> 5, c4 = (i & 31) << 2;
        *(float4*)(dst + (size_t)r * Sn + c4) = z;
    }
}

// ---------------------------------------------------------------------------
// K1: exp-scores. One block per (qt, bh) owns the whole tile row; Q resident,
// K tiles double-buffered via cp.async; epilogue = exp2 + causal mask + STG +
// per-row sum accumulation -> g_rowsum.
// SMEM: Qhi 0 | Qlo 32K | K0hi 64K | K0lo 96K | K1hi 128K | K1lo 160K  (192KB)
// ---------------------------------------------------------------------------
#define S1_QHI 0
#define S1_QLO 32768
#define S1_KHI(b) (65536 + (b) * 65536)
#define S1_KLO(b) (98304 + (b) * 65536)
#define S1_SZ  196608

__global__ __launch_bounds__(256, 1)
void k_scores_exp(float* __restrict__ attn)
{
    extern __shared__ char sm[];
    __shared__ float s_red[128];
    const uint32_t smb = smem_u32(sm);
    const int tid = threadIdx.x, wid = tid >> 5, lane = tid & 31;
    const int warp_m = wid & 3, warp_n = wid >> 2;

    const int qt = (NT - 1) - (int)blockIdx.x;    // big rows first
    const int bh = blockIdx.y;
    const int ke = qt + 1;

    // prologue: Q (group), K0 (group), K1 (group)
    cp_blob32k(smb + S1_QHI, g_Qhi + BLOB(bh, qt));
    cp_blob32k(smb + S1_QLO, g_Qlo + BLOB(bh, qt));
    CP_COMMIT();
    cp_blob32k(smb + S1_KHI(0), g_Khi + BLOB(bh, 0));
    cp_blob32k(smb + S1_KLO(0), g_Klo + BLOB(bh, 0));
    CP_COMMIT();
    if (ke > 1) {
        cp_blob32k(smb + S1_KHI(1), g_Khi + BLOB(bh, 1));
        cp_blob32k(smb + S1_KLO(1), g_Klo + BLOB(bh, 1));
        CP_COMMIT();
    }

    float part[4] = {0.f, 0.f, 0.f, 0.f};
    const int rb = warp_m * 32 + (lane >> 2);
    const int cb = warp_n * 64 + (lane & 3) * 2;

    for (int t = 0; t < ke; t++) {
        const int b = t & 1;
        if (t + 1 < ke) CP_WAIT(1); else CP_WAIT(0);
        __syncthreads();

        float acc[2][8][4];
        #pragma unroll
        for (int mf = 0; mf < 2; mf++)
            #pragma unroll
            for (int nf = 0; nf < 8; nf++)
                #pragma unroll
                for (int j = 0; j < 4; j++) acc[mf][nf][j] = 0.f;

        tile_mma(smb + S1_QHI, smb + S1_QLO, smb + S1_KHI(b), smb + S1_KLO(b),
                 acc, warp_m, warp_n, lane);
        __syncthreads();   // buf b free for reissue below

        if (t + 2 < ke) {
            cp_blob32k(smb + S1_KHI(b), g_Khi + BLOB(bh, t + 2));
            cp_blob32k(smb + S1_KLO(b), g_Klo + BLOB(bh, t + 2));
            CP_COMMIT();
        }

        // epilogue: exp2 (+mask on diagonal tile), STG, row partial sums
        float* dst = attn + ((size_t)bh * Sn + (size_t)qt * 128) * Sn + (size_t)t * 128;
        const bool diag = (t == qt);
        #pragma unroll
        for (int mf = 0; mf < 2; mf++) {
            const int r0 = rb + mf * 16, r1 = r0 + 8;
            #pragma unroll
            for (int nf = 0; nf < 8; nf++) {
                const int c = cb + nf * 8;
                float e00 = exp2f(acc[mf][nf][0]);
                float e01 = exp2f(acc[mf][nf][1]);
                float e10 = exp2f(acc[mf][nf][2]);
                float e11 = exp2f(acc[mf][nf][3]);
                if (diag) {
                    if (c     > r0) e00 = 0.f;
                    if (c + 1 > r0) e01 = 0.f;
                    if (c     > r1) e10 = 0.f;
                    if (c + 1 > r1) e11 = 0.f;
                }
                part[mf * 2 + 0] += e00 + e01;
                part[mf * 2 + 1] += e10 + e11;
                *(float2*)(dst + (size_t)r0 * Sn + c) = make_float2(e00, e01);
                *(float2*)(dst + (size_t)r1 * Sn + c) = make_float2(e10, e11);
            }
        }
    }

    // row-sum reduction (8 threads contribute per row)
    if (tid < 128) s_red[tid] = 0.f;
    __syncthreads();
    #pragma unroll
    for (int mf = 0; mf < 2; mf++) {
        atomicAdd(&s_red[rb + mf * 16],     part[mf * 2 + 0]);
        atomicAdd(&s_red[rb + mf * 16 + 8], part[mf * 2 + 1]);
    }
    __syncthreads();
    if (tid < 128)
        g_rowsum[((size_t)bh << 11) + qt * 128 + tid] = s_red[tid];
}

// ---------------------------------------------------------------------------
// K2: context + attn normalization. Reads exp tiles (cp.async raw stage),
// scales by 1/rowsum, writes normalized attn back, converts to bf16 hi/lo,
// GEMM against prepped V^T tiles. ctx written at epilogue.
// SMEM: raw 0..64K | Ahi 64K | Alo 96K | Vhi 128K | Vlo 160K  (192KB)
// ---------------------------------------------------------------------------
#define S2_RAW 0
#define S2_AHI 65536
#define S2_ALO 98304
#define S2_VHI 131072
#define S2_VLO 163840
#define S2_SZ  196608

__global__ __launch_bounds__(256, 1)
void k_context(float* __restrict__ attn, float* __restrict__ ctx)
{
    extern __shared__ char sm[];
    __shared__ float s_inv[128];
    const uint32_t smb = smem_u32(sm);
    const int tid = threadIdx.x, wid = tid >> 5, lane = tid & 31;
    const int warp_m = wid & 3, warp_n = wid >> 2;

    const int qt = (NT - 1) - (int)blockIdx.x;
    const int bh = blockIdx.y;

    if (tid < 128)
        s_inv[tid] = 1.0f / g_rowsum[((size_t)bh << 11) + qt * 128 + tid];

    float* arow = attn + ((size_t)bh * Sn + (size_t)qt * 128) * Sn;

    // prologue: raw exp tile 0 (64KB, 16 chunks/thread)
    {
        const float* src = arow;   // tile kt=0
        #pragma unroll
        for (int j = 0; j < 16; j++) {
            int i = tid + j * 256;
            int r = i >> 5, c4 = (i & 31) << 2;
            cpa16(smb + S2_RAW + (uint32_t)i * 16, src + (size_t)r * Sn + c4);
        }
        CP_COMMIT();
    }

    float acc[2][8][4];
    #pragma unroll
    for (int mf = 0; mf < 2; mf++)
        #pragma unroll
        for (int nf = 0; nf < 8; nf++)
            #pragma unroll
            for (int j = 0; j < 4; j++) acc[mf][nf][j] = 0.f;

    for (int t = 0; t <= qt; t++) {
        CP_WAIT(0);
        __syncthreads();   // raw[t] visible; V buffer free (post-MMA barrier)

        // issue V[t] (overlaps convert below)
        cp_blob32k(smb + S2_VHI, g_Vhi + BLOB(bh, t));
        cp_blob32k(smb + S2_VLO, g_Vlo + BLOB(bh, t));
        CP_COMMIT();

        // convert: normalize, write attn back, split to bf16 hi/lo
        float* dst = arow + (size_t)t * 128;
        #pragma unroll
        for (int j = 0; j < 16; j++) {
            int i = tid + j * 256;
            int r = i >> 5, c4 = (i & 31) << 2;
            float4 v = *(float4*)(sm + S2_RAW + i * 16);
            const float iv = s_inv[r];
            v.x *= iv; v.y *= iv; v.z *= iv; v.w *= iv;
            *(float4*)(dst + (size_t)r * Sn + c4) = v;
            uint32_t off = swz(r, c4);
            uint2 hp, lp;
            hp.x = pack2f(v.x, v.y); hp.y = pack2f(v.z, v.w);
            lp.x = pack2f(v.x - __bfloat162float(__float2bfloat16(v.x)),
                          v.y - __bfloat162float(__float2bfloat16(v.y)));
            lp.y = pack2f(v.z - __bfloat162float(__float2bfloat16(v.z)),
                          v.w - __bfloat162float(__float2bfloat16(v.w)));
            *(uint2*)(sm + S2_AHI + off) = hp;
            *(uint2*)(sm + S2_ALO + off) = lp;
        }
        __syncthreads();   // raw stage free; A tiles ready

        if (t < qt) {      // prefetch raw[t+1], overlaps MMA
            const float* src = arow + (size_t)(t + 1) * 128;
            #pragma unroll
            for (int j = 0; j < 16; j++) {
                int i = tid + j * 256;
                int r = i >> 5, c4 = (i & 31) << 2;
                cpa16(smb + S2_RAW + (uint32_t)i * 16, src + (size_t)r * Sn + c4);
            }
            CP_COMMIT();
            CP_WAIT(1);    // V[t] done (older group), raw[t+1] may be pending
        } else {
            CP_WAIT(0);
        }
        __syncthreads();

        tile_mma(smb + S2_AHI, smb + S2_ALO, smb + S2_VHI, smb + S2_VLO,
                 acc, warp_m, warp_n, lane);
        __syncthreads();   // A + V free before next iteration overwrites
    }

    float* dst = ctx + ((size_t)bh * Sn + (size_t)qt * 128) * DKn;
    const int rb = warp_m * 32 + (lane >> 2);
    const int cb = warp_n * 64 + (lane & 3) * 2;
    #pragma unroll
    for (int mf = 0; mf < 2; mf++)
        #pragma unroll
        for (int nf = 0; nf < 8; nf++) {
            float* p0 = dst + (size_t)(rb + mf * 16) * DKn + cb + nf * 8;
            float* p1 = p0 + 8 * DKn;
            *(float2*)p0 = make_float2(acc[mf][nf][0], acc[mf][nf][1]);
            *(float2*)p1 = make_float2(acc[mf][nf][2], acc[mf][nf][3]);
        }
}

// ---------------------------------------------------------------------------
extern "C" void kernel_launch(void* const* d_in, const int* in_sizes, int n_in,
                              void* d_out, int out_size)
{
    (void)in_sizes; (void)n_in; (void)out_size;
    const float* Q = (const float*)d_in[0];
    const float* K = (const float*)d_in[1];
    const float* V = (const float*)d_in[2];
    // d_in[3] = attn_mask (causal, known statically) — unused.

    float* out  = (float*)d_out;
    float* ctx  = out;
    float* attn = out + CTX_ELEMS;

    cudaFuncSetAttribute(k_scores_exp, cudaFuncAttributeMaxDynamicSharedMemorySize, S1_SZ);
    cudaFuncSetAttribute(k_context,    cudaFuncAttributeMaxDynamicSharedMemorySize, S2_SZ);

    k_prep_qk<<<dim3(2 * NT, NBH), 256>>>(Q, K);
    k_prep_v <<<dim3(NT, NBH), 256>>>(V);
    k_zero_upper<<<dim3((NT * (NT - 1)) / 2, NBH), 256>>>(attn);
    k_scores_exp<<<dim3(NT, NBH), 256, S1_SZ>>>(attn);
    k_context  <<<dim3(NT, NBH), 256, S2_SZ>>>(attn, ctx);
}